// round 6
// baseline (speedup 1.0000x reference)
#include <cuda_runtime.h>
#include <math.h>

#define BATCH 4
#define NQ    300
#define NC    80
#define NK    17
#define HW    4096
#define NWORDS 10                      // ceil(300/32)
#define BN    (BATCH*NQ)
#define TB    256
#define NSLICES (BATCH*NQ*NK)          // 20400
#define ARGB  884                      // persistent argmax blocks
#define GRID_TOTAL (BATCH + ARGB)      // 888 = 148 SMs * 6 blocks -> ONE wave
#define EPI   32                       // epilogue blocks

#define NEGV (-1000000000.0f)
#define IOU_THR   0.7f
#define SCORE_THR 0.01f

// scratch
__device__ float g_kpts[NSLICES * 3];  // per (b,n,k): nx, ny, maxval
__device__ int   g_sel[BN];            // selected original query per slot
__device__ int   g_done  = 0;
__device__ int   g_done2 = 0;

// ---- shared buffer layout (single buffer shared by both branches) ----
#define OFF_MASK   0          // u32 [NQ][NWORDS]  = 12000 B
#define OFF_OBOX   12000      // float4[NQ]        = 4800
#define OFF_BX1    16800
#define OFF_BY1    18000
#define OFF_BX2    19200
#define OFF_BY2    20400
#define OFF_OAREA  21600
#define OFF_SCORE  22800
#define OFF_SKEY   24000      // 16B aligned
#define OFF_LABEL  25200
#define OFF_ORDER  26400
#define OFF_VALIDA 27600
#define OFF_VS     27900
#define OFF_RED    28208      // float[32] / keepw u32[10]
#define OFF_MISC   28336      // s_maxc
#define SBUF_SIZE  28352

__global__ void __launch_bounds__(TB, 6)
fused_kernel(const float* __restrict__ logits,
             const float* __restrict__ boxes,
             const float* __restrict__ sizes,
             const float* __restrict__ hm,
             const float* __restrict__ off,
             float* __restrict__ out) {
    __shared__ __align__(16) unsigned char sbuf[SBUF_SIZE];
    __shared__ int s_rank;
    const int tid = threadIdx.x;

    if (blockIdx.x >= BATCH) {
        // ------- persistent heatmap argmax: ~23 slices/block, pipelined ------
        float* swv = (float*)(sbuf);                    // [8] per-warp max
        unsigned int* swi = (unsigned int*)(sbuf + 64); // [8] per-warp best idx
        const int a = blockIdx.x - BATCH;
        const int lane = tid & 31;
        const int wid  = tid >> 5;

        int s = a;
        const float4* p = reinterpret_cast<const float4*>(hm) + (size_t)s * (HW / 4);
        float4 v0 = p[tid];
        float4 v1 = p[tid + 256];
        float4 v2 = p[tid + 512];
        float4 v3 = p[tid + 768];

        while (s < NSLICES) {
            const int snext = s + ARGB;
            float4 n0, n1, n2, n3;
            if (snext < NSLICES) {
                const float4* pn = reinterpret_cast<const float4*>(hm)
                                   + (size_t)snext * (HW / 4);
                n0 = pn[tid];            // issued now; retire during reduce
                n1 = pn[tid + 256];
                n2 = pn[tid + 512];
                n3 = pn[tid + 768];
            }

            // fmax tree (short critical path)
            float m0 = fmaxf(fmaxf(v0.x, v0.y), fmaxf(v0.z, v0.w));
            float m1 = fmaxf(fmaxf(v1.x, v1.y), fmaxf(v1.z, v1.w));
            float m2 = fmaxf(fmaxf(v2.x, v2.y), fmaxf(v2.z, v2.w));
            float m3 = fmaxf(fmaxf(v3.x, v3.y), fmaxf(v3.z, v3.w));
            float m = fmaxf(fmaxf(m0, m1), fmaxf(m2, m3));
#pragma unroll
            for (int o = 16; o > 0; o >>= 1)
                m = fmaxf(m, __shfl_xor_sync(0xFFFFFFFFu, m, o));
            if (lane == 0) swv[wid] = m;
            __syncthreads();
            float M = fmaxf(fmaxf(fmaxf(swv[0], swv[1]), fmaxf(swv[2], swv[3])),
                            fmaxf(fmaxf(swv[4], swv[5]), fmaxf(swv[6], swv[7])));

            // lowest global index equal to M (descending scan => lowest wins)
            unsigned int bi = 0xFFFFFFFFu;
            const int b0 = tid * 4, b1 = (tid + 256) * 4,
                      b2 = (tid + 512) * 4, b3 = (tid + 768) * 4;
            if (v3.w == M) bi = b3 + 3;
            if (v3.z == M) bi = b3 + 2;
            if (v3.y == M) bi = b3 + 1;
            if (v3.x == M) bi = b3;
            if (v2.w == M) bi = b2 + 3;
            if (v2.z == M) bi = b2 + 2;
            if (v2.y == M) bi = b2 + 1;
            if (v2.x == M) bi = b2;
            if (v1.w == M) bi = b1 + 3;
            if (v1.z == M) bi = b1 + 2;
            if (v1.y == M) bi = b1 + 1;
            if (v1.x == M) bi = b1;
            if (v0.w == M) bi = b0 + 3;
            if (v0.z == M) bi = b0 + 2;
            if (v0.y == M) bi = b0 + 1;
            if (v0.x == M) bi = b0;
            bi = __reduce_min_sync(0xFFFFFFFFu, bi);
            if (lane == 0) swi[wid] = bi;
            __syncthreads();
            if (tid == 0) {
                unsigned int best = swi[0];
#pragma unroll
                for (int w = 1; w < 8; w++) best = min(best, swi[w]);
                float offx = off[(size_t)s * 2 + 0];
                float offy = off[(size_t)s * 2 + 1];
                float nx = (float)(best & 63) / 63.0f + offx;
                float ny = (float)(best >> 6) / 63.0f + offy;
                nx = fminf(fmaxf(nx, 0.0f), 1.0f);
                ny = fminf(fmaxf(ny, 0.0f), 1.0f);
                float* o = g_kpts + (size_t)s * 3;
                o[0] = nx; o[1] = ny; o[2] = M;
            }
            v0 = n0; v1 = n1; v2 = n2; v3 = n3;
            s = snext;
        }
    } else {
        // ---------------- NMS core: one block per batch ----------------------
        const int b = blockIdx.x;
        unsigned int* mask = (unsigned int*)(sbuf + OFF_MASK);   // [NQ][NWORDS]
        float4* obox  = (float4*)(sbuf + OFF_OBOX);
        float* bx1    = (float*)(sbuf + OFF_BX1);
        float* by1    = (float*)(sbuf + OFF_BY1);
        float* bx2    = (float*)(sbuf + OFF_BX2);
        float* by2    = (float*)(sbuf + OFF_BY2);
        float* oarea  = (float*)(sbuf + OFF_OAREA);
        float* score  = (float*)(sbuf + OFF_SCORE);
        float* skey   = (float*)(sbuf + OFF_SKEY);
        int*   label  = (int*)(sbuf + OFF_LABEL);
        int*   order  = (int*)(sbuf + OFF_ORDER);
        unsigned char* validA = (unsigned char*)(sbuf + OFF_VALIDA);
        unsigned char* vs     = (unsigned char*)(sbuf + OFF_VS);
        float* red    = (float*)(sbuf + OFF_RED);
        unsigned int* keepw = (unsigned int*)(sbuf + OFF_RED);   // reused
        float* s_maxc = (float*)(sbuf + OFF_MISC);

        const float s0 = sizes[b * 2 + 0];
        const float s1 = sizes[b * 2 + 1];

        // --- abs boxes + score/label ---
        float lmax = 0.0f;
        for (int n = tid; n < NQ; n += TB) {
            const float* pb = boxes + ((size_t)b * NQ + n) * 4;
            float cx = pb[0], cy = pb[1], w = pb[2], h = pb[3];
            float x1 = (cx - w / 2.0f) * s0;
            float y1 = (cy - h / 2.0f) * s1;
            float x2 = (cx + w / 2.0f) * s0;
            float y2 = (cy + h / 2.0f) * s1;
            bx1[n] = x1; by1[n] = y1; bx2[n] = x2; by2[n] = y2;
            lmax = fmaxf(lmax, fmaxf(fmaxf(fabsf(x1), fabsf(y1)),
                                     fmaxf(fabsf(x2), fabsf(y2))));
            const float4* pl4 = reinterpret_cast<const float4*>(
                logits + ((size_t)b * NQ + n) * NC);
            float bestv = -INFINITY;
            int   bl = 0;
#pragma unroll 4
            for (int c4 = 0; c4 < NC / 4; c4++) {
                float4 v = pl4[c4];
                int c = c4 * 4;
                if (v.x > bestv) { bestv = v.x; bl = c; }
                if (v.y > bestv) { bestv = v.y; bl = c + 1; }
                if (v.z > bestv) { bestv = v.z; bl = c + 2; }
                if (v.w > bestv) { bestv = v.w; bl = c + 3; }
            }
            float sc = 1.0f / (1.0f + expf(-bestv));
            score[n]  = sc;
            label[n]  = bl;
            bool valid = sc > SCORE_THR;
            validA[n] = valid ? 1 : 0;
            skey[n]   = valid ? sc : NEGV;
        }
#pragma unroll
        for (int o = 16; o > 0; o >>= 1)
            lmax = fmaxf(lmax, __shfl_down_sync(0xFFFFFFFFu, lmax, o));
        if ((tid & 31) == 0) red[tid >> 5] = lmax;
        __syncthreads();
        if (tid == 0) {
            float m = red[0];
#pragma unroll
            for (int w = 1; w < 8; w++) m = fmaxf(m, red[w]);
            *s_maxc = m + 1.0f;
        }
        __syncthreads();
        const float maxc = *s_maxc;

        // --- stable descending rank sort (== jnp.argsort(-s)) ---
        for (int i = tid; i < NQ; i += TB) {
            float si = skey[i];
            int r = 0;
            const float4* sk4 = reinterpret_cast<const float4*>(skey);
#pragma unroll 5
            for (int j4 = 0; j4 < NQ / 4; j4++) {
                float4 v = sk4[j4];
                int j = j4 * 4;
                r += (v.x > si) || (v.x == si && (j    ) < i);
                r += (v.y > si) || (v.y == si && (j + 1) < i);
                r += (v.z > si) || (v.z == si && (j + 2) < i);
                r += (v.w > si) || (v.w == si && (j + 3) < i);
            }
            order[r] = i;
        }
        __syncthreads();

        // --- sorted class-offset boxes ---
        for (int r = tid; r < NQ; r += TB) {
            int i = order[r];
            float o = (float)label[i] * maxc;
            float x1 = bx1[i] + o, y1 = by1[i] + o;
            float x2 = bx2[i] + o, y2 = by2[i] + o;
            obox[r] = make_float4(x1, y1, x2, y2);
            oarea[r] = (x2 - x1) * (y2 - y1);
            vs[r] = validA[i];
        }
        __syncthreads();

        // --- IoU bitmask, w-major: warp lanes share w -> broadcast LDS ---
        for (int u = tid; u < NQ * NWORDS; u += TB) {
            int i = u % NQ;
            int w = u / NQ;
            int j0 = w * 32;
            unsigned int bits = 0;
            if (j0 + 31 > i) {
                float4 bi4 = obox[i];
                float ai = oarea[i];
                int jend = (NQ - j0 < 32) ? (NQ - j0) : 32;
                for (int jj = 0; jj < jend; jj++) {
                    int j = j0 + jj;
                    if (j > i) {
                        float4 bj = obox[j];
                        float iw = fmaxf(fminf(bi4.z, bj.z) - fmaxf(bi4.x, bj.x), 0.0f);
                        float ih = fmaxf(fminf(bi4.w, bj.w) - fmaxf(bi4.y, bj.y), 0.0f);
                        float inter = iw * ih;
                        if (inter > 0.0f) {        // inter==0 -> iou==0 (exact)
                            float iou = inter / (ai + oarea[j] - inter + 1e-9f);
                            if (iou > IOU_THR) bits |= (1u << jj);
                        }
                    }
                }
            }
            mask[i * NWORDS + w] = bits;
        }
        __syncthreads();

        // --- greedy pass: warp 0, lane w owns suppression word w ---
        if (tid < 32) {
            const int lane = tid;
            unsigned int supp_w = 0, kw_w = 0;
            for (int i = 0; i < NQ; i++) {
                unsigned int sw = __shfl_sync(0xFFFFFFFFu, supp_w, i >> 5);
                unsigned int k = (unsigned int)vs[i] & (((sw >> (i & 31)) & 1u) ^ 1u);
                if (lane == (i >> 5)) kw_w |= k << (i & 31);
                unsigned int m = 0u - k;
                if (lane < NWORDS) supp_w |= mask[i * NWORDS + lane] & m;
            }
            if (lane < NWORDS) keepw[lane] = kw_w;
        }
        __syncthreads();

        // --- stable partition via popcount + write fl/fb/fs/vk, stash g_sel ---
        const int base = b * NQ;
        float* fl = out;
        float* fb = out + BN;
        float* fs = out + BN * 5;
        float* vk = out + BN * 6 + BN * NK * 3;

        for (int r = tid; r < NQ; r += TB) {
            int wq = r >> 5, bq = r & 31;
            int kb = 0, nk = 0;
#pragma unroll
            for (int w = 0; w < NWORDS; w++) {
                unsigned int kwv = keepw[w];
                nk += __popc(kwv);
                if (w < wq)  kb += __popc(kwv);
                if (w == wq) kb += __popc(kwv & ((1u << bq) - 1u));
            }
            bool kf = (keepw[wq] >> bq) & 1u;
            int m = kf ? kb : (nk + (r - kb));
            int q = order[r];
            g_sel[base + m] = q;
            vk[base + m] = kf ? 1.0f : 0.0f;
            fl[base + m] = kf ? (float)label[q] : -1.0f;
            fs[base + m] = kf ? score[q] : 0.0f;
            float* pb = fb + (size_t)(base + m) * 4;
            pb[0] = kf ? bx1[q] : 0.0f;
            pb[1] = kf ? by1[q] : 0.0f;
            pb[2] = kf ? bx2[q] : 0.0f;
            pb[3] = kf ? by2[q] : 0.0f;
        }
    }

    // ------------- distributed last-EPI-blocks epilogue: keypoint gather -----
    __threadfence();
    __syncthreads();
    if (tid == 0) s_rank = atomicAdd(&g_done, 1);
    __syncthreads();
    const int rank = s_rank;
    if (rank >= GRID_TOTAL - EPI) {
        if (tid == 0) {
            while (atomicAdd(&g_done, 0) < GRID_TOTAL) {}
        }
        __syncthreads();
        __threadfence();
        float* ak = out + BN * 6;
        const float* vk = out + BN * 6 + BN * NK * 3;
        const float* fb = out + BN;
        const int er = rank - (GRID_TOTAL - EPI);
        for (int idx = er * TB + tid; idx < NSLICES; idx += EPI * TB) {
            int k  = idx % NK;
            int bm = idx / NK;                 // b*NQ + m
            float* o = ak + (size_t)idx * 3;
            if (vk[bm] != 0.0f) {
                int bq = bm / NQ;
                int q = g_sel[bm];
                const float* kp = g_kpts + ((size_t)(bq * NQ + q) * NK + k) * 3;
                const float* pb = fb + (size_t)bm * 4;
                float x1 = pb[0], y1 = pb[1], x2 = pb[2], y2 = pb[3];
                o[0] = x1 + kp[0] * (x2 - x1);
                o[1] = y1 + kp[1] * (y2 - y1);
                o[2] = kp[2];
            } else {
                o[0] = 0.0f; o[1] = 0.0f; o[2] = 0.0f;
            }
        }
        __threadfence();
        __syncthreads();
        if (tid == 0) {
            int o2 = atomicAdd(&g_done2, 1);
            if (o2 == EPI - 1) { g_done = 0; g_done2 = 0; }   // reset for replay
        }
    }
}

// ---------------------------------------------------------------------------
extern "C" void kernel_launch(void* const* d_in, const int* in_sizes, int n_in,
                              void* d_out, int out_size) {
    const float* logits = (const float*)d_in[0];   // (4,300,80)
    const float* boxes  = (const float*)d_in[1];   // (4,300,4)
    const float* hm     = (const float*)d_in[2];   // (4,300,17,64,64)
    const float* off    = (const float*)d_in[3];   // (4,300,17,2)
    const float* sizes  = (const float*)d_in[4];   // (4,2)
    float* out = (float*)d_out;

    fused_kernel<<<GRID_TOTAL, TB>>>(logits, boxes, sizes, hm, off, out);
}

// round 7
// speedup vs baseline: 1.0921x; 1.0921x over previous
#include <cuda_runtime.h>
#include <math.h>

#define BATCH 4
#define NQ    300
#define NC    80
#define NK    17
#define HW    4096
#define NWORDS 10                      // ceil(300/32)
#define BN    (BATCH*NQ)
#define TB    256
#define NSLICES (BATCH*NQ*NK)          // 20400
#define ARGB  588                      // persistent argmax blocks
#define GRID_TOTAL (BATCH + ARGB)      // 592 = 148 SMs * 4 blocks -> ONE wave
#define EPI   32                       // epilogue blocks

#define NEGV (-1000000000.0f)
#define IOU_THR   0.7f
#define SCORE_THR 0.01f

// scratch
__device__ float g_kpts[NSLICES * 3];  // per (b,n,k): nx, ny, maxval
__device__ int   g_sel[BN];            // selected original query per slot
__device__ int   g_done  = 0;
__device__ int   g_done2 = 0;

// ---- shared buffer layout (single buffer shared by both branches) ----
#define OFF_MASK   0          // u32 [NQ][NWORDS]  = 12000 B
#define OFF_OBOX   12000      // float4[NQ]        = 4800
#define OFF_BX1    16800
#define OFF_BY1    18000
#define OFF_BX2    19200
#define OFF_BY2    20400
#define OFF_OAREA  21600
#define OFF_SCORE  22800
#define OFF_SKEY   24000      // 16B aligned
#define OFF_LABEL  25200
#define OFF_ORDER  26400
#define OFF_VALIDA 27600
#define OFF_VS     27900
#define OFF_RED    28208      // float[32] / keepw u32[10]
#define OFF_MISC   28336      // s_maxc
#define SBUF_SIZE  28352

__global__ void __launch_bounds__(TB, 4)
fused_kernel(const float* __restrict__ logits,
             const float* __restrict__ boxes,
             const float* __restrict__ sizes,
             const float* __restrict__ hm,
             const float* __restrict__ off,
             float* __restrict__ out) {
    __shared__ __align__(16) unsigned char sbuf[SBUF_SIZE];
    __shared__ int s_rank;
    const int tid = threadIdx.x;

    if (blockIdx.x >= BATCH) {
        // ---- persistent heatmap argmax, depth-2 slice prefetch (MLP=8) -----
        float* swv = (float*)(sbuf);                    // [8] per-warp max
        unsigned int* swi = (unsigned int*)(sbuf + 64); // [8] per-warp best idx
        const int a = blockIdx.x - BATCH;
        const int lane = tid & 31;
        const int wid  = tid >> 5;
        const float4* hm4 = reinterpret_cast<const float4*>(hm);

        int s = a;
        // buffer 0: current slice
        float4 v0, v1, v2, v3;
        {
            const float4* p = hm4 + (size_t)s * (HW / 4);
            v0 = p[tid]; v1 = p[tid + 256]; v2 = p[tid + 512]; v3 = p[tid + 768];
        }
        // buffer 1: slice s+ARGB (always in range: ARGB + (ARGB-1) < NSLICES)
        float4 u0, u1, u2, u3;
        {
            const float4* p = hm4 + (size_t)(s + ARGB) * (HW / 4);
            u0 = p[tid]; u1 = p[tid + 256]; u2 = p[tid + 512]; u3 = p[tid + 768];
        }

        while (s < NSLICES) {
            // issue prefetch for s + 2*ARGB (depth-2)
            float4 w0, w1, w2, w3;
            const int s2 = s + 2 * ARGB;
            if (s2 < NSLICES) {
                const float4* p = hm4 + (size_t)s2 * (HW / 4);
                w0 = p[tid]; w1 = p[tid + 256]; w2 = p[tid + 512]; w3 = p[tid + 768];
            }

            // ---- reduce current slice (v*) ----
            float m0 = fmaxf(fmaxf(v0.x, v0.y), fmaxf(v0.z, v0.w));
            float m1 = fmaxf(fmaxf(v1.x, v1.y), fmaxf(v1.z, v1.w));
            float m2 = fmaxf(fmaxf(v2.x, v2.y), fmaxf(v2.z, v2.w));
            float m3 = fmaxf(fmaxf(v3.x, v3.y), fmaxf(v3.z, v3.w));
            float m = fmaxf(fmaxf(m0, m1), fmaxf(m2, m3));
#pragma unroll
            for (int o = 16; o > 0; o >>= 1)
                m = fmaxf(m, __shfl_xor_sync(0xFFFFFFFFu, m, o));
            if (lane == 0) swv[wid] = m;
            __syncthreads();
            float M = fmaxf(fmaxf(fmaxf(swv[0], swv[1]), fmaxf(swv[2], swv[3])),
                            fmaxf(fmaxf(swv[4], swv[5]), fmaxf(swv[6], swv[7])));

            // lowest global index equal to M (descending scan => lowest wins)
            unsigned int bi = 0xFFFFFFFFu;
            const int b0 = tid * 4, b1 = (tid + 256) * 4,
                      b2 = (tid + 512) * 4, b3 = (tid + 768) * 4;
            if (v3.w == M) bi = b3 + 3;
            if (v3.z == M) bi = b3 + 2;
            if (v3.y == M) bi = b3 + 1;
            if (v3.x == M) bi = b3;
            if (v2.w == M) bi = b2 + 3;
            if (v2.z == M) bi = b2 + 2;
            if (v2.y == M) bi = b2 + 1;
            if (v2.x == M) bi = b2;
            if (v1.w == M) bi = b1 + 3;
            if (v1.z == M) bi = b1 + 2;
            if (v1.y == M) bi = b1 + 1;
            if (v1.x == M) bi = b1;
            if (v0.w == M) bi = b0 + 3;
            if (v0.z == M) bi = b0 + 2;
            if (v0.y == M) bi = b0 + 1;
            if (v0.x == M) bi = b0;
            bi = __reduce_min_sync(0xFFFFFFFFu, bi);
            if (lane == 0) swi[wid] = bi;
            __syncthreads();
            if (tid == 0) {
                unsigned int best = swi[0];
#pragma unroll
                for (int w = 1; w < 8; w++) best = min(best, swi[w]);
                float offx = off[(size_t)s * 2 + 0];
                float offy = off[(size_t)s * 2 + 1];
                float nx = (float)(best & 63) / 63.0f + offx;
                float ny = (float)(best >> 6) / 63.0f + offy;
                nx = fminf(fmaxf(nx, 0.0f), 1.0f);
                ny = fminf(fmaxf(ny, 0.0f), 1.0f);
                float* o = g_kpts + (size_t)s * 3;
                o[0] = nx; o[1] = ny; o[2] = M;
            }
            // rotate buffers
            v0 = u0; v1 = u1; v2 = u2; v3 = u3;
            u0 = w0; u1 = w1; u2 = w2; u3 = w3;
            s += ARGB;
        }
    } else {
        // ---------------- NMS core: one block per batch ----------------------
        const int b = blockIdx.x;
        unsigned int* mask = (unsigned int*)(sbuf + OFF_MASK);   // [NQ][NWORDS]
        float4* obox  = (float4*)(sbuf + OFF_OBOX);
        float* bx1    = (float*)(sbuf + OFF_BX1);
        float* by1    = (float*)(sbuf + OFF_BY1);
        float* bx2    = (float*)(sbuf + OFF_BX2);
        float* by2    = (float*)(sbuf + OFF_BY2);
        float* oarea  = (float*)(sbuf + OFF_OAREA);
        float* score  = (float*)(sbuf + OFF_SCORE);
        float* skey   = (float*)(sbuf + OFF_SKEY);
        int*   label  = (int*)(sbuf + OFF_LABEL);
        int*   order  = (int*)(sbuf + OFF_ORDER);
        unsigned char* validA = (unsigned char*)(sbuf + OFF_VALIDA);
        unsigned char* vs     = (unsigned char*)(sbuf + OFF_VS);
        float* red    = (float*)(sbuf + OFF_RED);
        unsigned int* keepw = (unsigned int*)(sbuf + OFF_RED);   // reused
        float* s_maxc = (float*)(sbuf + OFF_MISC);

        const float s0 = sizes[b * 2 + 0];
        const float s1 = sizes[b * 2 + 1];

        // --- abs boxes + score/label ---
        float lmax = 0.0f;
        for (int n = tid; n < NQ; n += TB) {
            const float* pb = boxes + ((size_t)b * NQ + n) * 4;
            float cx = pb[0], cy = pb[1], w = pb[2], h = pb[3];
            float x1 = (cx - w / 2.0f) * s0;
            float y1 = (cy - h / 2.0f) * s1;
            float x2 = (cx + w / 2.0f) * s0;
            float y2 = (cy + h / 2.0f) * s1;
            bx1[n] = x1; by1[n] = y1; bx2[n] = x2; by2[n] = y2;
            lmax = fmaxf(lmax, fmaxf(fmaxf(fabsf(x1), fabsf(y1)),
                                     fmaxf(fabsf(x2), fabsf(y2))));
            const float4* pl4 = reinterpret_cast<const float4*>(
                logits + ((size_t)b * NQ + n) * NC);
            float bestv = -INFINITY;
            int   bl = 0;
#pragma unroll 4
            for (int c4 = 0; c4 < NC / 4; c4++) {
                float4 v = pl4[c4];
                int c = c4 * 4;
                if (v.x > bestv) { bestv = v.x; bl = c; }
                if (v.y > bestv) { bestv = v.y; bl = c + 1; }
                if (v.z > bestv) { bestv = v.z; bl = c + 2; }
                if (v.w > bestv) { bestv = v.w; bl = c + 3; }
            }
            float sc = 1.0f / (1.0f + expf(-bestv));
            score[n]  = sc;
            label[n]  = bl;
            bool valid = sc > SCORE_THR;
            validA[n] = valid ? 1 : 0;
            skey[n]   = valid ? sc : NEGV;
        }
#pragma unroll
        for (int o = 16; o > 0; o >>= 1)
            lmax = fmaxf(lmax, __shfl_down_sync(0xFFFFFFFFu, lmax, o));
        if ((tid & 31) == 0) red[tid >> 5] = lmax;
        __syncthreads();
        if (tid == 0) {
            float m = red[0];
#pragma unroll
            for (int w = 1; w < 8; w++) m = fmaxf(m, red[w]);
            *s_maxc = m + 1.0f;
        }
        __syncthreads();
        const float maxc = *s_maxc;

        // --- stable descending rank sort (== jnp.argsort(-s)) ---
        for (int i = tid; i < NQ; i += TB) {
            float si = skey[i];
            int r = 0;
            const float4* sk4 = reinterpret_cast<const float4*>(skey);
#pragma unroll 5
            for (int j4 = 0; j4 < NQ / 4; j4++) {
                float4 v = sk4[j4];
                int j = j4 * 4;
                r += (v.x > si) || (v.x == si && (j    ) < i);
                r += (v.y > si) || (v.y == si && (j + 1) < i);
                r += (v.z > si) || (v.z == si && (j + 2) < i);
                r += (v.w > si) || (v.w == si && (j + 3) < i);
            }
            order[r] = i;
        }
        __syncthreads();

        // --- sorted class-offset boxes ---
        for (int r = tid; r < NQ; r += TB) {
            int i = order[r];
            float o = (float)label[i] * maxc;
            float x1 = bx1[i] + o, y1 = by1[i] + o;
            float x2 = bx2[i] + o, y2 = by2[i] + o;
            obox[r] = make_float4(x1, y1, x2, y2);
            oarea[r] = (x2 - x1) * (y2 - y1);
            vs[r] = validA[i];
        }
        __syncthreads();

        // --- IoU bitmask, w-major: warp lanes share w -> broadcast LDS ---
        for (int u = tid; u < NQ * NWORDS; u += TB) {
            int i = u % NQ;
            int w = u / NQ;
            int j0 = w * 32;
            unsigned int bits = 0;
            if (j0 + 31 > i) {
                float4 bi4 = obox[i];
                float ai = oarea[i];
                int jend = (NQ - j0 < 32) ? (NQ - j0) : 32;
                for (int jj = 0; jj < jend; jj++) {
                    int j = j0 + jj;
                    if (j > i) {
                        float4 bj = obox[j];
                        float iw = fmaxf(fminf(bi4.z, bj.z) - fmaxf(bi4.x, bj.x), 0.0f);
                        float ih = fmaxf(fminf(bi4.w, bj.w) - fmaxf(bi4.y, bj.y), 0.0f);
                        float inter = iw * ih;
                        if (inter > 0.0f) {        // inter==0 -> iou==0 (exact)
                            float iou = inter / (ai + oarea[j] - inter + 1e-9f);
                            if (iou > IOU_THR) bits |= (1u << jj);
                        }
                    }
                }
            }
            mask[i * NWORDS + w] = bits;
        }
        __syncthreads();

        // --- greedy pass: warp 0, lane w owns suppression word w ---
        if (tid < 32) {
            const int lane = tid;
            unsigned int supp_w = 0, kw_w = 0;
            for (int i = 0; i < NQ; i++) {
                unsigned int sw = __shfl_sync(0xFFFFFFFFu, supp_w, i >> 5);
                unsigned int k = (unsigned int)vs[i] & (((sw >> (i & 31)) & 1u) ^ 1u);
                if (lane == (i >> 5)) kw_w |= k << (i & 31);
                unsigned int m = 0u - k;
                if (lane < NWORDS) supp_w |= mask[i * NWORDS + lane] & m;
            }
            if (lane < NWORDS) keepw[lane] = kw_w;
        }
        __syncthreads();

        // --- stable partition via popcount + write fl/fb/fs/vk, stash g_sel ---
        const int base = b * NQ;
        float* fl = out;
        float* fb = out + BN;
        float* fs = out + BN * 5;
        float* vk = out + BN * 6 + BN * NK * 3;

        for (int r = tid; r < NQ; r += TB) {
            int wq = r >> 5, bq = r & 31;
            int kb = 0, nk = 0;
#pragma unroll
            for (int w = 0; w < NWORDS; w++) {
                unsigned int kwv = keepw[w];
                nk += __popc(kwv);
                if (w < wq)  kb += __popc(kwv);
                if (w == wq) kb += __popc(kwv & ((1u << bq) - 1u));
            }
            bool kf = (keepw[wq] >> bq) & 1u;
            int m = kf ? kb : (nk + (r - kb));
            int q = order[r];
            g_sel[base + m] = q;
            vk[base + m] = kf ? 1.0f : 0.0f;
            fl[base + m] = kf ? (float)label[q] : -1.0f;
            fs[base + m] = kf ? score[q] : 0.0f;
            float* pb = fb + (size_t)(base + m) * 4;
            pb[0] = kf ? bx1[q] : 0.0f;
            pb[1] = kf ? by1[q] : 0.0f;
            pb[2] = kf ? bx2[q] : 0.0f;
            pb[3] = kf ? by2[q] : 0.0f;
        }
    }

    // ------------- distributed last-EPI-blocks epilogue: keypoint gather -----
    __threadfence();
    __syncthreads();
    if (tid == 0) s_rank = atomicAdd(&g_done, 1);
    __syncthreads();
    const int rank = s_rank;
    if (rank >= GRID_TOTAL - EPI) {
        if (tid == 0) {
            while (atomicAdd(&g_done, 0) < GRID_TOTAL) {}
        }
        __syncthreads();
        __threadfence();
        float* ak = out + BN * 6;
        const float* vk = out + BN * 6 + BN * NK * 3;
        const float* fb = out + BN;
        const int er = rank - (GRID_TOTAL - EPI);
        for (int idx = er * TB + tid; idx < NSLICES; idx += EPI * TB) {
            int k  = idx % NK;
            int bm = idx / NK;                 // b*NQ + m
            float* o = ak + (size_t)idx * 3;
            if (vk[bm] != 0.0f) {
                int bq = bm / NQ;
                int q = g_sel[bm];
                const float* kp = g_kpts + ((size_t)(bq * NQ + q) * NK + k) * 3;
                const float* pb = fb + (size_t)bm * 4;
                float x1 = pb[0], y1 = pb[1], x2 = pb[2], y2 = pb[3];
                o[0] = x1 + kp[0] * (x2 - x1);
                o[1] = y1 + kp[1] * (y2 - y1);
                o[2] = kp[2];
            } else {
                o[0] = 0.0f; o[1] = 0.0f; o[2] = 0.0f;
            }
        }
        __threadfence();
        __syncthreads();
        if (tid == 0) {
            int o2 = atomicAdd(&g_done2, 1);
            if (o2 == EPI - 1) { g_done = 0; g_done2 = 0; }   // reset for replay
        }
    }
}

// ---------------------------------------------------------------------------
extern "C" void kernel_launch(void* const* d_in, const int* in_sizes, int n_in,
                              void* d_out, int out_size) {
    const float* logits = (const float*)d_in[0];   // (4,300,80)
    const float* boxes  = (const float*)d_in[1];   // (4,300,4)
    const float* hm     = (const float*)d_in[2];   // (4,300,17,64,64)
    const float* off    = (const float*)d_in[3];   // (4,300,17,2)
    const float* sizes  = (const float*)d_in[4];   // (4,2)
    float* out = (float*)d_out;

    fused_kernel<<<GRID_TOTAL, TB>>>(logits, boxes, sizes, hm, off, out);
}